// round 7
// baseline (speedup 1.0000x reference)
#include <cuda_runtime.h>

#define Bn   16
#define Tn   262144
#define HOP  256
#define WINL 1024
#define PADL 384
#define Fn   1024
#define Pn   22
#define NGRP 512            // frame groups (32 frames each)
#define SPAN 8960           // per-group OLA span
#define STRIPL 768          // seam width
#define NCHUNK 20           // 640 samples / 32 per segment
#define SEGB_T0 384         // segB start time (256-sample warm-up)
#define WARM_CHUNKS 8       // segB chunks with t < 640 (discarded)

// Cross-group seam partial sums
__device__ float d_strip_lo[NGRP][STRIPL];
__device__ float d_strip_hi[NGRP][STRIPL];

typedef unsigned long long ull;

static __device__ __forceinline__ ull pk2(float lo, float hi) {
    ull r; asm("mov.b64 %0,{%1,%2};" : "=l"(r) : "f"(lo), "f"(hi)); return r;
}
static __device__ __forceinline__ void upk2(float& lo, float& hi, ull v) {
    asm("mov.b64 {%0,%1},%2;" : "=f"(lo), "=f"(hi) : "l"(v));
}
static __device__ __forceinline__ ull fma2_(ull a, ull b, ull c) {
    ull r; asm("fma.rn.f32x2 %0,%1,%2,%3;" : "=l"(r) : "l"(a), "l"(b), "l"(c)); return r;
}
static __device__ __forceinline__ ull mul2_(ull a, ull b) {
    ull r; asm("mul.rn.f32x2 %0,%1,%2;" : "=l"(r) : "l"(a), "l"(b)); return r;
}
static __device__ __forceinline__ ull add2_(ull a, ull b) {
    ull r; asm("add.rn.f32x2 %0,%1,%2;" : "=l"(r) : "l"(a), "l"(b)); return r;
}

static __device__ __forceinline__ float hannf(int t) {
    return 0.5f - 0.5f * __cosf(6.283185307179586f * (float)t * (1.0f / 1024.0f));
}

// smem (floats): acc[SPAN] | xs[2][32*34] | tile[2][32*34]
#define XS_F 1088
#define SMEM_FLOATS (SPAN + 4 * XS_F)
#define SMEM_BYTES  (SMEM_FLOATS * 4)

// ---------------------------------------------------------------------------
// Kernel 1: one CTA (64 threads = 2 warps) per 32-frame group.
//   warp0 computes samples [0,640); warp1 starts at 384 with zero state,
//   discards 256 warm-up samples, emits [640,1024). Recurrence is explicitly
//   software-pipelined: RA/RE carry the H[1..10] dot partials one block ahead
//   so only ONE fma2 sits on the block-to-block critical path.
// ---------------------------------------------------------------------------
__global__ void __launch_bounds__(64)
lpc_ola_kernel(const float* __restrict__ ex,
               const float* __restrict__ gain,
               const float* __restrict__ a,
               float* __restrict__ out) {
    extern __shared__ float smem[];

    const int warp = threadIdx.x >> 5;       // 0 = segA, 1 = segB
    const int lane = threadIdx.x & 31;
    const int gw   = blockIdx.x;              // frame group 0..511
    const int s0   = gw * 32;
    const int s    = s0 + lane;                // this lane's sequence
    const int b    = s >> 10;
    const int ww   = gw & 31;                  // group index within batch
    const int f0   = ww * 32;                  // base frame

    float* __restrict__ acc = smem;
    float* __restrict__ xsw = smem + SPAN + warp * XS_F;
    float* __restrict__ tlw = smem + SPAN + 2 * XS_F + warp * XS_F;

    // zero shared accumulator
    for (int i = threadIdx.x; i < SPAN / 4; i += 64)
        ((float4*)acc)[i] = make_float4(0.f, 0.f, 0.f, 0.f);

    const float g = gain[s];

    // c[q] = -a[q-1] (q=1..22), c[23]=c[24]=0
    float c[25];
    #pragma unroll
    for (int p = 0; p < Pn; ++p) c[p + 1] = -a[s * Pn + p];
    c[23] = 0.0f; c[24] = 0.0f;
    const float c1 = c[1];

    // CA[k] = (c_{2k+1}, c_{2k+2}) for y0's dot;
    // CE[k] = (c_{2k+2}, c_{2k+3}) for y1's shifted dot (y1 = c1*y0 + g*x1 + dotE)
    ull CA[11], CE[11], H[11];
    #pragma unroll
    for (int k = 0; k < 11; ++k) {
        CA[k] = pk2(c[2 * k + 1], c[2 * k + 2]);
        CE[k] = pk2(c[2 * k + 2], c[2 * k + 3]);
        H[k]  = 0ull;
    }
    ull RA = 0ull, RE = 0ull;   // pipelined partials (zero state -> zero)
    __syncthreads();

    const float* __restrict__ exb = ex + b * Tn;
    const int tbase = warp ? SEGB_T0 : 0;

    // prefetch chunk 0 (coalesced: lane sweeps time, r sweeps frames)
    float xr[32];
    #pragma unroll
    for (int r = 0; r < 32; ++r) {
        int idx = (f0 + r) * HOP + tbase + lane - PADL;
        xr[r] = ((unsigned)idx < (unsigned)Tn) ? exb[idx] : 0.0f;
    }

    for (int cc = 0; cc < NCHUNK; ++cc) {
        const int t0 = tbase + 32 * cc;

        // commit prefetched chunk to this warp's xs
        #pragma unroll
        for (int r = 0; r < 32; ++r) xsw[r * 34 + lane] = xr[r];
        __syncwarp();

        // prefetch next chunk; latency hides under recurrence
        if (cc < NCHUNK - 1) {
            const int t1 = t0 + 32;
            #pragma unroll
            for (int r = 0; r < 32; ++r) {
                int idx = (f0 + r) * HOP + t1 + lane - PADL;
                xr[r] = ((unsigned)idx < (unsigned)Tn) ? exb[idx] : 0.0f;
            }
        }

        // 16 blocks x 2 samples, software-pipelined packed dots
        const float* xrow = xsw + lane * 34;
        float2 xp2 = *(const float2*)xrow;
        #pragma unroll
        for (int bk = 0; bk < 16; ++bk) {
            float2 xn2;
            if (bk < 15) xn2 = *(const float2*)(xrow + 2 * bk + 2);
            const float x0 = xp2.x, x1 = xp2.y;

            // complete this block's dots: single fma2 from newest pair
            const ull accA = fma2_(CA[0], H[0], RA);
            const ull accE = fma2_(CE[0], H[0], RE);

            // start next block's partials (independent of this block's outputs)
            ull rae = mul2_(CA[2], H[1]);
            ull ree = mul2_(CE[2], H[1]);
            rae = fma2_(CA[4],  H[3], rae);  ree = fma2_(CE[4],  H[3], ree);
            rae = fma2_(CA[6],  H[5], rae);  ree = fma2_(CE[6],  H[5], ree);
            rae = fma2_(CA[8],  H[7], rae);  ree = fma2_(CE[8],  H[7], ree);
            rae = fma2_(CA[10], H[9], rae);  ree = fma2_(CE[10], H[9], ree);
            ull rao = mul2_(CA[1], H[0]);
            ull reo = mul2_(CE[1], H[0]);
            rao = fma2_(CA[3], H[2], rao);   reo = fma2_(CE[3], H[2], reo);
            rao = fma2_(CA[5], H[4], rao);   reo = fma2_(CE[5], H[4], reo);
            rao = fma2_(CA[7], H[6], rao);   reo = fma2_(CE[7], H[6], reo);
            rao = fma2_(CA[9], H[8], rao);   reo = fma2_(CE[9], H[8], reo);
            RA = add2_(rae, rao);
            RE = add2_(ree, reo);

            // tail (short serial path)
            float aLo, aHi, eLo, eHi;
            upk2(aLo, aHi, accA);
            upk2(eLo, eHi, accE);
            const float y0 = fmaf(g, x0, aLo + aHi);
            const float y1 = fmaf(c1, y0, fmaf(g, x1, eLo + eHi));

            *(float2*)(tlw + lane * 34 + 2 * bk) = make_float2(y0, y1);

            #pragma unroll
            for (int k = 10; k > 0; --k) H[k] = H[k - 1];
            H[0] = pk2(y1, y0);

            xp2 = xn2;
        }
        __syncwarp();

        // windowed OLA accumulate (skip segB warm-up chunks)
        if (warp == 0 || cc >= WARM_CHUNKS) {
            const float wv = hannf(t0 + lane);
            #pragma unroll
            for (int r = 0; r < 32; ++r)
                acc[r * HOP + t0 + lane] += tlw[r * 34 + lane] * wv;
        }
        __syncwarp();
    }
    __syncthreads();

    // interior [768, 8192): all 4 contributions local; norm == 2 exactly
    float* __restrict__ outb = out + (size_t)b * Tn + ww * 8192 + 384;
    const float4* __restrict__ acc4 = (const float4*)(acc + STRIPL);
    for (int i = threadIdx.x; i < (8192 - STRIPL) / 4; i += 64) {
        float4 v = acc4[i];
        v.x *= 0.5f; v.y *= 0.5f; v.z *= 0.5f; v.w *= 0.5f;
        ((float4*)outb)[i] = v;
    }
    // seams for kernel 2
    for (int j = threadIdx.x; j < STRIPL; j += 64) {
        d_strip_lo[gw][j] = acc[j];
        d_strip_hi[gw][j] = acc[8192 + j];
    }
}

// ---------------------------------------------------------------------------
// Kernel 2: resolve seams. One block per region, 192 threads, float4/thread
//   (MLP>=2). Non-edge seams have norm == 2 exactly; batch edges use hann.
// ---------------------------------------------------------------------------
__global__ void __launch_bounds__(192)
strip_kernel(float* __restrict__ out) {
    const int rg = blockIdx.x;
    const int q  = threadIdx.x;        // float4 index 0..191

    if (rg < NGRP) {
        const int w  = rg;
        const int ww = w & 31;
        const int bI = w >> 5;
        const int pbase = ww * 8192;
        const float4 lo4 = ((const float4*)d_strip_lo[w])[q];
        if (ww > 0) {                  // interior seam: norm exactly 2
            const float4 hi4 = ((const float4*)d_strip_hi[w - 1])[q];
            float4 v;
            v.x = (lo4.x + hi4.x) * 0.5f;
            v.y = (lo4.y + hi4.y) * 0.5f;
            v.z = (lo4.z + hi4.z) * 0.5f;
            v.w = (lo4.w + hi4.w) * 0.5f;
            *(float4*)(out + (size_t)bI * Tn + pbase + 4 * q - PADL) = v;
            return;
        }
        // batch-leading edge: per element with window norms
        const float sv[4] = {lo4.x, lo4.y, lo4.z, lo4.w};
        #pragma unroll
        for (int e = 0; e < 4; ++e) {
            const int p = pbase + 4 * q + e;
            const int o = p - PADL;
            if ((unsigned)o >= (unsigned)Tn) continue;
            const int fhi = p >> 8;
            float norm = 0.0f;
            #pragma unroll
            for (int k = 0; k < 4; ++k) {
                const int ff = fhi - k;
                if (ff >= 0 && ff < Fn) norm += hannf(p - ff * HOP);
            }
            out[(size_t)bI * Tn + o] = sv[e] / norm;
        }
    } else {
        const int w = ((rg - NGRP) << 5) | 31;   // batch-trailing edge
        const int bI = w >> 5;
        const int pbase = 32 * 8192;
        const float4 hi4 = ((const float4*)d_strip_hi[w])[q];
        const float sv[4] = {hi4.x, hi4.y, hi4.z, hi4.w};
        #pragma unroll
        for (int e = 0; e < 4; ++e) {
            const int p = pbase + 4 * q + e;
            const int o = p - PADL;
            if ((unsigned)o >= (unsigned)Tn) continue;
            const int fhi = p >> 8;
            float norm = 0.0f;
            #pragma unroll
            for (int k = 0; k < 4; ++k) {
                const int ff = fhi - k;
                if (ff >= 0 && ff < Fn) norm += hannf(p - ff * HOP);
            }
            out[(size_t)bI * Tn + o] = sv[e] / norm;
        }
    }
}

// ---------------------------------------------------------------------------
extern "C" void kernel_launch(void* const* d_in, const int* in_sizes, int n_in,
                              void* d_out, int out_size) {
    const float* ex   = (const float*)d_in[0];
    const float* gain = (const float*)d_in[1];
    const float* a    = (const float*)d_in[2];
    float* out = (float*)d_out;

    cudaFuncSetAttribute(lpc_ola_kernel,
                         cudaFuncAttributeMaxDynamicSharedMemorySize, SMEM_BYTES);
    lpc_ola_kernel<<<NGRP, 64, SMEM_BYTES>>>(ex, gain, a, out);
    strip_kernel<<<NGRP + Bn, 192>>>(out);
}